// round 15
// baseline (speedup 1.0000x reference)
#include <cuda_runtime.h>
#include <cstdint>

// ---------------------------------------------------------------------------
// Shapes (fixed): B=4, N=M=P=2048, NS=1024
//   d_in[0] pc1_0 [4,2048,3]  d_in[1] pc1_1 [4,1024,3]  d_in[2] pc1_3 [4,2048,1]
//   d_in[3] pc2   [4,2048,3]  d_in[4] pc3   [4,2048,3]  out [4,2048,2048] f32
//
// out[b,n,m] = S + 0.5*dist(pc1_0[b,n], pc2[b,m])
// S = conf + 0.5*cd(flat pc1_0||pc2) + seed_cd(flat pc1_1||pc2)
//
// nn_dual computes each chamfer matrix ONCE extracting row-min AND col-min
// (100.7M pairs x 4 fma-ops vs 201M x 3 one-directional). Conflict-free smem
// indexing this time; results merged via int-atomicMin (d2 >= 0 so float bits
// are order-preserving) -> finalize is depth-1.
// ---------------------------------------------------------------------------

// g_min layout (int-encoded nonneg floats), 36864 entries total:
//  [0,8192)      cd  dir1: per pc2 j,   min over pc1_0
//  [8192,16384)  cd  dir2: per pc1_0 a, min over pc2
//  [16384,24576) seed dir1: per pc2 j,  min over pc1_1
//  [24576,28672) seed dir2: per pc1_1 a,min over pc2
//  [28672,36864) conf: per (b,p) pc3 point, min over pc2[b]
__device__ int   g_min[36864];
__device__ float g_scal[3];    // [0]=cd [1]=seed [2]=conf

__device__ __forceinline__ float fsqrt_ap(float x) {
    float r; asm("sqrt.approx.f32 %0,%1;" : "=f"(r) : "f"(x)); return r;
}

// -------------------------------- init --------------------------------------
__global__ void __launch_bounds__(256) init_kernel() {
    const int i = blockIdx.x * 256 + threadIdx.x;
    g_min[i] = 0x7F7FFFFF;             // FLT_MAX bits
    if (i < 3) g_scal[i] = 0.0f;
}

// ------------------------- dual-min tiled NN pass ----------------------------
// 1536 blocks x 256 threads (tx=16, ty=16).
// Block = (cloud, A-chunk of 128, B-seg of 512 pc2 pts = 2 tiles of 256).
// Thread: 8 A rows x 16 B cols per tile. amin[8] in regs across the seg;
// per-B col-min reduced per tile via shfl(ty-pair) + smem(8 warps), then
// atomicMin to g_min. d = r2 - 2a.r (3 FFMA); u = d + a2 (FADD) for col-min.
__global__ void __launch_bounds__(256) nn_dual(const float* __restrict__ pc10,
                                               const float* __restrict__ pc11,
                                               const float* __restrict__ pc2)
{
    __shared__ float4 sA[128];
    __shared__ float4 sB[256];
    __shared__ float  sRed[8][256];
    const int t  = threadIdx.x;
    const int tx = t & 15, ty = t >> 4;
    int l = blockIdx.x;

    const float* A; int* g1; int* g2; int achunk, seg;
    if (l < 1024) {            // cd: A=pc1_0 (64 chunks x 16 segs)
        achunk = l >> 4; seg = l & 15; A = pc10;
        g1 = g_min;          g2 = g_min + 8192;
    } else {                   // seed: A=pc1_1 (32 chunks x 16 segs)
        l -= 1024;
        achunk = l >> 4; seg = l & 15; A = pc11;
        g1 = g_min + 16384;  g2 = g_min + 24576;
    }
    const int abase = achunk * 128;
    const int bbase = seg * 512;

    // ---- stage A chunk ----
    if (t < 128) {
        const float* ap = A + 3 * (abase + t);
        const float x = ap[0], y = ap[1], z = ap[2];
        sA[t] = make_float4(x, y, z, x * x + y * y + z * z);
    }
    __syncthreads();

    // ---- 8 A rows to registers (broadcast reads, conflict-free) ----
    float nax[8], nay[8], naz[8], aa[8], amin[8];
    #pragma unroll
    for (int i = 0; i < 8; i++) {
        const float4 a = sA[ty * 8 + i];
        nax[i] = -2.f * a.x; nay[i] = -2.f * a.y; naz[i] = -2.f * a.z;
        aa[i] = a.w;
        amin[i] = 3.0e38f;
    }

    // ---- 2 B tiles of 256 ----
    #pragma unroll
    for (int tile = 0; tile < 2; tile++) {
        {
            const float* bp = pc2 + 3 * (bbase + tile * 256 + t);
            const float x = bp[0], y = bp[1], z = bp[2];
            sB[t] = make_float4(x, y, z, x * x + y * y + z * z);
        }
        __syncthreads();

        #pragma unroll 4
        for (int j0 = 0; j0 < 16; j0++) {
            const float4 b = sB[j0 * 16 + tx];   // 16 distinct, 2-way bcast
            float bm = 3.0e38f;
            #pragma unroll
            for (int i = 0; i < 8; i++) {
                const float d = fmaf(nax[i], b.x, fmaf(nay[i], b.y,
                                fmaf(naz[i], b.z, b.w)));
                amin[i] = fminf(amin[i], d);          // + aa[i] folded at end
                bm = fminf(bm, d + aa[i]);            // true d2 for col-min
            }
            bm = fminf(bm, __shfl_xor_sync(0xffffffffu, bm, 16)); // merge ty pair
            if ((ty & 1) == 0) sRed[ty >> 1][j0 * 16 + tx] = bm;
        }
        __syncthreads();

        {   // 8-warp column reduce -> atomicMin (dir1)
            float m = sRed[0][t];
            #pragma unroll
            for (int k = 1; k < 8; k++) m = fminf(m, sRed[k][t]);
            atomicMin(&g1[bbase + tile * 256 + t],
                      __float_as_int(fmaxf(m, 0.0f)));
        }
        // next tile: sB rewrite is safe (all past j0 loop); sRed rewrite is
        // guarded by the post-staging __syncthreads().
    }

    // ---- amin: reduce across 16 tx lanes, write dir2 ----
    #pragma unroll
    for (int i = 0; i < 8; i++) {
        float v = amin[i];
        v = fminf(v, __shfl_xor_sync(0xffffffffu, v, 1));
        v = fminf(v, __shfl_xor_sync(0xffffffffu, v, 2));
        v = fminf(v, __shfl_xor_sync(0xffffffffu, v, 4));
        v = fminf(v, __shfl_xor_sync(0xffffffffu, v, 8));
        if (tx == 0)
            atomicMin(&g2[abase + ty * 8 + i],
                      __float_as_int(fmaxf(v + aa[i], 0.0f)));
    }
}

// --------------------------- conf NN pass (1-dir) ----------------------------
// 64 blocks x 256 threads (proven): per-b, q=pc3 over R=pc2; atomicMin.
__global__ void __launch_bounds__(256) conf_kernel(const float* __restrict__ pc2,
                                                   const float* __restrict__ pc3)
{
    __shared__ float4 tile[512];
    const int t = threadIdx.x;
    const int l = blockIdx.x;
    const int b = l >> 4;
    const int r = l & 15;
    const int qb = r >> 2, rc = r & 3;
    const float* Q = pc3 + b * 6144;
    const float* R = pc2 + b * 6144;
    int* gm = g_min + 28672 + b * 2048;

    {
        const float* rp = R + (size_t)rc * 1536;
        #pragma unroll
        for (int j = 0; j < 2; j++) {
            const int idx = t + j * 256;
            const float x = rp[3 * idx], y = rp[3 * idx + 1], z = rp[3 * idx + 2];
            tile[idx] = make_float4(x, y, z, x * x + y * y + z * z);
        }
    }

    const int q0 = qb * 512 + t;
    const int q1 = q0 + 256;
    const float ax0 = Q[3 * q0], ay0 = Q[3 * q0 + 1], az0 = Q[3 * q0 + 2];
    const float ax1 = Q[3 * q1], ay1 = Q[3 * q1 + 1], az1 = Q[3 * q1 + 2];
    const float a20 = ax0 * ax0 + ay0 * ay0 + az0 * az0;
    const float a21 = ax1 * ax1 + ay1 * ay1 + az1 * az1;
    const float nax0 = -2.f * ax0, nay0 = -2.f * ay0, naz0 = -2.f * az0;
    const float nax1 = -2.f * ax1, nay1 = -2.f * ay1, naz1 = -2.f * az1;

    float m0a = 3.0e38f, m0b = 3.0e38f, m1a = 3.0e38f, m1b = 3.0e38f;
    __syncthreads();

    #pragma unroll 4
    for (int g = 0; g < 512; g += 2) {
        const float4 r0 = tile[g];
        const float4 r1 = tile[g + 1];
        m0a = fminf(m0a, fmaf(nax0, r0.x, fmaf(nay0, r0.y, fmaf(naz0, r0.z, r0.w))));
        m1a = fminf(m1a, fmaf(nax1, r0.x, fmaf(nay1, r0.y, fmaf(naz1, r0.z, r0.w))));
        m0b = fminf(m0b, fmaf(nax0, r1.x, fmaf(nay0, r1.y, fmaf(naz0, r1.z, r1.w))));
        m1b = fminf(m1b, fmaf(nax1, r1.x, fmaf(nay1, r1.y, fmaf(naz1, r1.z, r1.w))));
    }

    atomicMin(&gm[q0], __float_as_int(fmaxf(fminf(m0a, m0b) + a20, 0.0f)));
    atomicMin(&gm[q1], __float_as_int(fmaxf(fminf(m1a, m1b) + a21, 0.0f)));
}

// ------------------------------ finalize ------------------------------------
// 36864 threads, 1:1 with g_min -> sqrt -> weighted sums into g_scal.
__global__ void __launch_bounds__(256) finalize_kernel(const float* __restrict__ pc13)
{
    __shared__ float s[3];
    if (threadIdx.x < 3) s[threadIdx.x] = 0.0f;
    __syncthreads();

    const int i = blockIdx.x * 256 + threadIdx.x;
    const float m = __int_as_float(g_min[i]);
    float val; int cat;
    if (i < 16384)      { val = sqrtf(m) * (1.0f / 8192.0f); cat = 0; }   // cd
    else if (i < 24576) { val = sqrtf(m) * (1.0f / 8192.0f); cat = 1; }   // seed d1
    else if (i < 28672) { val = sqrtf(m) * (1.0f / 4096.0f); cat = 1; }   // seed d2
    else {                                                                // conf
        const int q = i - 28672;
        const float gt = expf(-sqrtf(m));
        const float df = pc13[q] - gt;
        val = df * df * (1.0f / 8192.0f); cat = 2;
    }
    atomicAdd(&s[cat], val);
    __syncthreads();
    if (threadIdx.x < 3) atomicAdd(&g_scal[threadIdx.x], s[threadIdx.x]);
}

// ------------------------------ out kernel ----------------------------------
// 4096 blocks x 256 threads. Block = (b, col-half, 4-row chunk); thread owns
// 4 pc2 points. Queries pre-staged in smem in parallel; scalar FFMA + MUFU
// sqrt; 1 STG.128 per row.
__global__ void __launch_bounds__(256) out_kernel(const float* __restrict__ pc10,
                                                  const float* __restrict__ pc2,
                                                  float* __restrict__ out)
{
    __shared__ float4 qs[4];             // per n: {nax, nay, naz, a2}
    const int t = threadIdx.x;
    const int b    = blockIdx.x >> 10;
    const int rem  = blockIdx.x & 1023;
    const int half = rem >> 9;
    const int nc   = rem & 511;
    const int nbase = b * 2048 + nc * 4;
    const int mbase = half * 1024 + t * 4;

    float Gx[4], Gy[4], Gz[4], Gr[4];
    {
        float F[12];
        const float4* rp = (const float4*)(pc2 + (size_t)b * 6144 + mbase * 3);
        #pragma unroll
        for (int j = 0; j < 3; j++) {
            const float4 f = rp[j];
            F[4 * j] = f.x; F[4 * j + 1] = f.y;
            F[4 * j + 2] = f.z; F[4 * j + 3] = f.w;
        }
        #pragma unroll
        for (int g = 0; g < 4; g++) {
            Gx[g] = F[3 * g]; Gy[g] = F[3 * g + 1]; Gz[g] = F[3 * g + 2];
            Gr[g] = Gx[g] * Gx[g] + Gy[g] * Gy[g] + Gz[g] * Gz[g];
        }
    }

    if (t < 4) {
        const int n = nbase + t;
        const float x = pc10[3 * n], y = pc10[3 * n + 1], z = pc10[3 * n + 2];
        qs[t] = make_float4(-2.f * x, -2.f * y, -2.f * z, x * x + y * y + z * z);
    }
    const float S = g_scal[2] + 0.5f * g_scal[0] + g_scal[1];
    __syncthreads();

    float* orow = out + (size_t)nbase * 2048 + mbase;
    #pragma unroll
    for (int n = 0; n < 4; n++) {
        const float4 q = qs[n];
        float res[4];
        #pragma unroll
        for (int g = 0; g < 4; g++) {
            const float d2 = fmaf(q.x, Gx[g], fmaf(q.y, Gy[g],
                             fmaf(q.z, Gz[g], Gr[g] + q.w)));
            res[g] = fmaf(0.5f, fsqrt_ap(fmaxf(d2, 0.0f)), S);
        }
        *(float4*)orow = make_float4(res[0], res[1], res[2], res[3]);
        orow += 2048;
    }
}

// ------------------------------ launcher ------------------------------------
extern "C" void kernel_launch(void* const* d_in, const int* in_sizes, int n_in,
                              void* d_out, int out_size)
{
    const float* pc10 = (const float*)d_in[0];
    const float* pc11 = (const float*)d_in[1];
    const float* pc13 = (const float*)d_in[2];
    const float* pc2  = (const float*)d_in[3];
    const float* pc3  = (const float*)d_in[4];
    float* out = (float*)d_out;

    init_kernel<<<144, 256>>>();
    nn_dual<<<1536, 256>>>(pc10, pc11, pc2);
    conf_kernel<<<64, 256>>>(pc2, pc3);
    finalize_kernel<<<144, 256>>>(pc13);
    out_kernel<<<4096, 256>>>(pc10, pc2, out);
}